// round 16
// baseline (speedup 1.0000x reference)
#include <cuda_runtime.h>
#include <cuda_fp16.h>
#include <cstdint>

#define B_   8192
#define N_   40
#define F_   256
#define NF   10240
#define TOT  83886080

// ---------------- device scratch (no allocation allowed) --------------------
__device__ __align__(256) __half g_S[TOT];         // S = input @ W  (fp16)
__device__ __align__(256) __half g_Yh[TOT];        // Y = adjblk @ S (fp16)
__device__ __align__(256) __half g_Whi[F_ * F_];   // K-major [fout][fin]
__device__ float g_spY[4 * 64 * 2 * 2560];         // [i][bg][stat][r*256+f]
__device__ float g_spY2[40 * 8 * 2 * 256];         // [n][y][stat][col]
__device__ float g_scale[NF];
__device__ float g_shift[NF];

// ---------------- helpers ---------------------------------------------------
__device__ __forceinline__ uint32_t smem_u32(const void* p) {
    uint32_t a;
    asm("{ .reg .u64 t; cvta.to.shared.u64 t, %1; cvt.u32.u64 %0, t; }" : "=r"(a) : "l"(p));
    return a;
}
__device__ __forceinline__ void cp16(uint32_t dst, const void* src) {
    asm volatile("cp.async.cg.shared.global [%0], [%1], 16;" :: "r"(dst), "l"(src));
}
#define CP_COMMIT() asm volatile("cp.async.commit_group;" ::: "memory")
#define CP_WAIT(n)  asm volatile("cp.async.wait_group %0;" :: "n"(n) : "memory")

#define LDSM4(r, addr)                                                          \
    asm volatile("ldmatrix.sync.aligned.m8n8.x4.shared.b16 {%0,%1,%2,%3}, [%4];"\
        : "=r"((r)[0]), "=r"((r)[1]), "=r"((r)[2]), "=r"((r)[3]) : "r"(addr))

#define MMA(c, a, b)                                                            \
    asm volatile("mma.sync.aligned.m16n8k16.row.col.f32.f16.f16.f32 "           \
        "{%0,%1,%2,%3}, {%4,%5,%6,%7}, {%8,%9}, {%0,%1,%2,%3};"                 \
        : "+f"((c)[0]), "+f"((c)[1]), "+f"((c)[2]), "+f"((c)[3])                \
        : "r"((a)[0]), "r"((a)[1]), "r"((a)[2]), "r"((a)[3]),                   \
          "r"((b)[0]), "r"((b)[1]))

__device__ __forceinline__ uint32_t h2u(__half2 h) { return *(uint32_t*)&h; }

// ---------------------------------------------------------------------------
// K0: W [fin][fout] fp32 -> fp16 K-major [fout][fin]
// ---------------------------------------------------------------------------
__global__ void k0_wprep(const float* __restrict__ W) {
    int k = blockIdx.x, n = threadIdx.x;
    g_Whi[n * 256 + k] = __float2half_rn(W[k * 256 + n]);
}

// ---------------------------------------------------------------------------
// KS: S = input @ W, single-pass fp16 HMMA, 512 threads / 16 warps.
// A converted fp32->fp16 IN REGISTERS (16 regs staging, no F smem stage).
// Warp tile 32m x 64n (acc 64 regs). CTA = 128 rows x 256 cols. grid 2560.
// smem: [B resident 131072][H fp16 double-buffer 2 x 16384] = 163840.
// ---------------------------------------------------------------------------
#define SMEM_KS 163840
#define SM_H 131072

__global__ __launch_bounds__(512, 1) void kS_gemm(const float* __restrict__ input) {
    extern __shared__ char smem[];
    const uint32_t sb = smem_u32(smem);
    const int tid = threadIdx.x, lane = tid & 31, wid = tid >> 5;
    const int wr = wid >> 2;           // 0..3  row group (x32)
    const int wc = wid & 3;            // 0..3  col group (x64)
    const size_t rowBase = (size_t)blockIdx.x * 128;

    // ---- resident B: [kcc 4][256 rows x 128B, swizzled] ----
    {
        const char* bB = (const char*)g_Whi;
#pragma unroll
        for (int it = 0; it < 16; ++it) {
            int u = it * 512 + tid;
            int kcc = u >> 11, r = (u >> 3) & 255, o = u & 7;
            size_t gb = (size_t)r * 512 + (size_t)kcc * 128 + o * 16;
            uint32_t so = (uint32_t)kcc * 32768 + r * 128 + ((o ^ (r & 7)) << 4);
            cp16(sb + so, bB + gb);
        }
        CP_COMMIT();
    }

    // ---- A path: LDG fp32 (4 x float4) -> cvt -> swizzled fp16 STS ----
    auto ldgA = [&](int kcc, float4* p) {
#pragma unroll
        for (int it = 0; it < 4; ++it) {
            int u = it * 512 + tid;                 // 0..2047 16B units
            int row = u >> 4, o = u & 15;
            p[it] = *(const float4*)(input + (rowBase + row) * 256 +
                                     (size_t)kcc * 64 + o * 4);
        }
    };
    auto stsA = [&](int buf, const float4* p) {
        char* hb = smem + SM_H + buf * 16384;
#pragma unroll
        for (int it = 0; it < 4; ++it) {
            int u = it * 512 + tid;
            int row = u >> 4, o = u & 15;
            uint2 w;
            w.x = h2u(__floats2half2_rn(p[it].x, p[it].y));
            w.y = h2u(__floats2half2_rn(p[it].z, p[it].w));
            *(uint2*)(hb + (uint32_t)row * 128 +
                      ((((uint32_t)o >> 1) ^ (uint32_t)(row & 7)) << 4) +
                      (uint32_t)(o & 1) * 8) = w;
        }
    };

    {
        float4 p0[4];
        ldgA(0, p0);
        stsA(0, p0);
    }
    CP_WAIT(0);           // B resident landed
    __syncthreads();      // H0 + B visible to all

    float acc[2][8][4];
#pragma unroll
    for (int mt = 0; mt < 2; ++mt)
#pragma unroll
        for (int nt = 0; nt < 8; ++nt)
#pragma unroll
            for (int q = 0; q < 4; ++q) acc[mt][nt][q] = 0.f;

    const int aRow0 = wr * 32 + (lane & 15);
    const int aKU = lane >> 4;
    const int aSw = lane & 7;
    const int bN0 = wc * 64 + (lane & 7) + ((lane >> 4) & 1) * 8;
    const int bKU = (lane >> 3) & 1;

#pragma unroll
    for (int kcc = 0; kcc < 4; ++kcc) {
        float4 pn[4];
        if (kcc < 3) ldgA(kcc + 1, pn);            // LDG in flight over MMAs

        const uint32_t as = sb + SM_H + (uint32_t)(kcc & 1) * 16384;
        const uint32_t bs = sb + (uint32_t)kcc * 32768;
#pragma unroll
        for (int kk = 0; kk < 4; ++kk) {
            uint32_t ahi[2][4];
#pragma unroll
            for (int mt = 0; mt < 2; ++mt) {
                uint32_t off = (uint32_t)(aRow0 + mt * 16) * 128 +
                               (uint32_t)(((kk * 2 + aKU) ^ aSw) << 4);
                LDSM4(ahi[mt], as + off);
            }
#pragma unroll
            for (int half = 0; half < 2; ++half) {
                uint32_t bf[4][2];
#pragma unroll
                for (int p = 0; p < 2; ++p) {
                    uint32_t off = (uint32_t)(bN0 + half * 32 + p * 16) * 128 +
                                   (uint32_t)(((kk * 2 + bKU) ^ aSw) << 4);
                    uint32_t r[4];
                    LDSM4(r, bs + off);
                    bf[2 * p][0] = r[0]; bf[2 * p][1] = r[1];
                    bf[2 * p + 1][0] = r[2]; bf[2 * p + 1][1] = r[3];
                }
#pragma unroll
                for (int mt = 0; mt < 2; ++mt)
#pragma unroll
                    for (int q = 0; q < 4; ++q)
                        MMA(acc[mt][half * 4 + q], ahi[mt], bf[q]);
            }
        }
        if (kcc < 3) stsA((kcc + 1) & 1, pn);      // write other buffer
        __syncthreads();
    }

    // ---- epilogue: stage fp16 S (swizzled, B region dead) -> coalesced out --
    char* yst = smem + 8192;
    {
        const int rl = wr * 32 + (lane >> 2);
        const int cq = (lane & 3) * 2;
#pragma unroll
        for (int mt = 0; mt < 2; ++mt)
#pragma unroll
            for (int h = 0; h < 2; ++h) {
                const int row = rl + mt * 16 + h * 8;
                const uint32_t sw = (uint32_t)(row & 7) << 4;
#pragma unroll
                for (int nt = 0; nt < 8; ++nt) {
                    const int col = wc * 64 + nt * 8 + cq;
                    __half2 hv = __floats2half2_rn(acc[mt][nt][2 * h],
                                                   acc[mt][nt][2 * h + 1]);
                    *(__half2*)(yst + ((uint32_t)row * 512 + (((uint32_t)col * 2) ^ sw))) = hv;
                }
            }
    }
    __syncthreads();
    {
        char* sg = (char*)g_S + rowBase * 512;
#pragma unroll
        for (int i = 0; i < 8; ++i) {
            int u = tid + 512 * i;
            int row = u >> 5, o = (u & 31) * 16;
            uint4 v = *(const uint4*)(yst + (uint32_t)row * 512 +
                                      ((uint32_t)o ^ ((uint32_t)(row & 7) << 4)));
            *(uint4*)(sg + (size_t)row * 512 + o) = v;
        }
    }
}

// ---------------------------------------------------------------------------
// KY: Y[b, s+r, f] = sum_c adj[b,s+r,s+c] * S[b,s+c,f]; fp16 Y out + stats.
// grid (4 blocks, 64 bgs of 128 batches), 256 threads (one per f).
// ---------------------------------------------------------------------------
__global__ __launch_bounds__(256, 1) void kY_apply(const float* __restrict__ adj) {
    __shared__ float sadj[128][100];
    const int i = blockIdx.x, s = i * 10;
    const int bg = blockIdx.y;
    const int f = threadIdx.x;

    for (int u = f; u < 12800; u += 256) {
        int bi = u / 100, rc = u % 100;
        int b = bg * 128 + bi;
        sadj[bi][rc] = adj[((size_t)b * 40 + s + rc / 10) * 40 + s + rc % 10];
    }
    __syncthreads();

    float st[10], st2[10];
#pragma unroll
    for (int r = 0; r < 10; ++r) { st[r] = 0.f; st2[r] = 0.f; }

    for (int bi = 0; bi < 128; ++bi) {
        const int b = bg * 128 + bi;
        const __half* sp = g_S + ((size_t)b * 40 + s) * 256 + f;
        float x[10];
#pragma unroll
        for (int c = 0; c < 10; ++c) x[c] = __half2float(sp[c * 256]);
        __half* yp = g_Yh + ((size_t)b * 40 + s) * 256 + f;
#pragma unroll
        for (int r = 0; r < 10; ++r) {
            float y = 0.f;
#pragma unroll
            for (int c = 0; c < 10; ++c) y = fmaf(sadj[bi][r * 10 + c], x[c], y);
            yp[r * 256] = __float2half_rn(y);
            st[r] += y;
            st2[r] = fmaf(y, y, st2[r]);
        }
    }
    float* gp = g_spY + (size_t)(i * 64 + bg) * 5120;
#pragma unroll
    for (int r = 0; r < 10; ++r) {
        gp[r * 256 + f] = st[r];
        gp[2560 + r * 256 + f] = st2[r];
    }
}

// ---------------------------------------------------------------------------
// K3b1: fold 8 bgs per group. grid (40, 8), 256 threads.
// ---------------------------------------------------------------------------
__global__ void k3b1_fold() {
    const int n = blockIdx.x, y = blockIdx.y, col = threadIdx.x;
    const int i = n / 10, r = n % 10;
    float s = 0.f, s2 = 0.f;
#pragma unroll
    for (int j = 0; j < 8; ++j) {
        const float* gp = g_spY + (size_t)(i * 64 + y * 8 + j) * 5120 + r * 256 + col;
        s += gp[0];
        s2 += gp[2560];
    }
    float* o = g_spY2 + (size_t)(n * 8 + y) * 512;
    o[col] = s;
    o[256 + col] = s2;
}

// K3b2: final fold -> scale/shift. grid 40, 256 threads.
__global__ void k3b2_scaleshift(const float* __restrict__ gamma,
                                const float* __restrict__ beta) {
    const int n = blockIdx.x, col = threadIdx.x;
    const int i = n / 10;
    float s = 0.f, s2 = 0.f;
#pragma unroll
    for (int y = 0; y < 8; ++y) {
        const float* gp = g_spY2 + (size_t)(n * 8 + y) * 512;
        s += gp[col];
        s2 += gp[256 + col];
    }
    const float inv = 1.f / (float)B_;
    float mean = s * inv;
    float var = fmaxf(s2 * inv - mean * mean, 0.f);
    int nf = n * 256 + col;
    float sc = gamma[i * NF + nf] * rsqrtf(var + 1e-5f);
    float bsum = beta[nf] + beta[NF + nf] + beta[2 * NF + nf] + beta[3 * NF + nf];
    g_scale[nf] = sc;
    g_shift[nf] = fmaf(-mean, sc, bsum);
}

// ---------------------------------------------------------------------------
// K4: out = Yh * scale + shift (fp16 read, fp32 write). 8 elems/thread.
// ---------------------------------------------------------------------------
__global__ void k4_normalize(float* __restrict__ out) {
    const size_t gid = (size_t)blockIdx.x * blockDim.x + threadIdx.x;
    uint4 raw = ((const uint4*)g_Yh)[gid];
    const int col8 = (int)(gid & 31);
    const int grow = (int)(gid >> 5);
    const int n = grow % 40;
    const float* scp = g_scale + n * 256 + col8 * 8;
    const float* shp = g_shift + n * 256 + col8 * 8;
    float4 sc0 = *(const float4*)scp, sc1 = *(const float4*)(scp + 4);
    float4 sh0 = *(const float4*)shp, sh1 = *(const float4*)(shp + 4);
    const __half2* hp = (const __half2*)&raw;
    float2 f0 = __half22float2(hp[0]);
    float2 f1 = __half22float2(hp[1]);
    float2 f2 = __half22float2(hp[2]);
    float2 f3 = __half22float2(hp[3]);
    float4 o0, o1;
    o0.x = fmaf(f0.x, sc0.x, sh0.x);
    o0.y = fmaf(f0.y, sc0.y, sh0.y);
    o0.z = fmaf(f1.x, sc0.z, sh0.z);
    o0.w = fmaf(f1.y, sc0.w, sh0.w);
    o1.x = fmaf(f2.x, sc1.x, sh1.x);
    o1.y = fmaf(f2.y, sc1.y, sh1.y);
    o1.z = fmaf(f3.x, sc1.z, sh1.z);
    o1.w = fmaf(f3.y, sc1.w, sh1.w);
    float* op = out + (size_t)grow * 256 + col8 * 8;
    *(float4*)op = o0;
    *(float4*)(op + 4) = o1;
}

// ---------------------------------------------------------------------------
extern "C" void kernel_launch(void* const* d_in, const int* in_sizes, int n_in,
                              void* d_out, int out_size) {
    const float* input = (const float*)d_in[0];
    const float* adj   = (const float*)d_in[1];
    const float* W     = (const float*)d_in[2];
    const float* gamma = (const float*)d_in[3];
    const float* beta  = (const float*)d_in[4];
    float* out = (float*)d_out;

    static bool inited = false;
    if (!inited) {
        cudaFuncSetAttribute(kS_gemm, cudaFuncAttributeMaxDynamicSharedMemorySize, SMEM_KS);
        inited = true;
    }

    k0_wprep<<<256, 256>>>(W);
    kS_gemm<<<2560, 512, SMEM_KS>>>(input);
    kY_apply<<<dim3(4, 64), 256>>>(adj);
    k3b1_fold<<<dim3(40, 8), 256>>>();
    k3b2_scaleshift<<<40, 256>>>(gamma, beta);
    k4_normalize<<<(TOT / 8) / 256, 256>>>(out);
}